// round 17
// baseline (speedup 1.0000x reference)
#include <cuda_runtime.h>
#include <cuda_bf16.h>
#include <mma.h>
#include <math.h>

using namespace nvcuda;

typedef unsigned long long u64;

#define B_   32
#define S_   197
#define D_   384
#define H_   6
#define HD_  64
#define HID_ 1024
#define SD_  75648           // S*D
#define BS_  6304            // B*S
#define BSPAD_ 6400          // padded rows for wmma tile overrun
#define BH_  192             // B*H
#define SHD_ 12608           // S*HD
#define SPLITK_ 197
#define KCH_ 384             // SD / SPLITK

// ---------------- scratch (static device globals, zero-initialized) ----------------
__device__ float g_x[B_ * SD_];                     // LN(images) fp32 (for residual)
__device__ __nv_bfloat16 g_x_hi[BSPAD_ * D_];       // bf16 split of g_x, [row][384]
__device__ __nv_bfloat16 g_x_lo[BSPAD_ * D_];
__device__ float g_qkv[3 * BH_ * SHD_];             // [mat][b*H+h][s*HD+e]
__device__ float g_skip[B_ * SD_];                  // attn out + residual
__device__ __nv_bfloat16 g_y_hi[B_ * SD_];          // bf16 split of LN(skip), [32][75648]
__device__ __nv_bfloat16 g_y_lo[B_ * SD_];
__device__ float g_part[SPLITK_ * B_ * HID_];
__device__ __nv_bfloat16 g_h_hi[B_ * HID_];         // bf16 split of gelu(y@W1+b1), [32][1024]
__device__ __nv_bfloat16 g_h_lo[B_ * HID_];

// ---------------- packed f32x2 helpers (attention) ----------------
__device__ __forceinline__ u64 pack2(float a, float b) {
    u64 u;
    asm("mov.b64 %0, {%1, %2};" : "=l"(u) : "r"(__float_as_uint(a)), "r"(__float_as_uint(b)));
    return u;
}
__device__ __forceinline__ float2 unpack2(u64 u) {
    unsigned int lo, hi;
    asm("mov.b64 {%0, %1}, %2;" : "=r"(lo), "=r"(hi) : "l"(u));
    return make_float2(__uint_as_float(lo), __uint_as_float(hi));
}
#define FMA2(d, a, b) asm("fma.rn.f32x2 %0, %1, %2, %0;" : "+l"(d) : "l"(a), "l"(b))

__device__ __forceinline__ void split_bf16(float v, __nv_bfloat16& h, __nv_bfloat16& l) {
    h = __float2bfloat16(v);
    l = __float2bfloat16(v - __bfloat162float(h));
}

// ---------------- LayerNorm reduction helper ----------------
__device__ __forceinline__ void ln_stats(const float* __restrict__ in, int n,
                                         float& mu_out, float& rs_out) {
    double s = 0.0, s2 = 0.0;
    for (int i = threadIdx.x; i < n; i += blockDim.x) {
        float v = in[i];
        s  += (double)v;
        s2 += (double)v * (double)v;
    }
    __shared__ double rs[32], rs2[32];
    __shared__ float smu, srs;
    int lane = threadIdx.x & 31, wid = threadIdx.x >> 5;
#pragma unroll
    for (int o = 16; o; o >>= 1) {
        s  += __shfl_xor_sync(0xffffffffu, s, o);
        s2 += __shfl_xor_sync(0xffffffffu, s2, o);
    }
    if (lane == 0) { rs[wid] = s; rs2[wid] = s2; }
    __syncthreads();
    if (threadIdx.x == 0) {
        int nw = blockDim.x >> 5;
        double ts = 0.0, ts2 = 0.0;
        for (int i = 0; i < nw; i++) { ts += rs[i]; ts2 += rs2[i]; }
        double mu  = ts / n;
        double var = ts2 / n - mu * mu;
        smu = (float)mu;
        srs = rsqrtf((float)var + 1e-5f);
    }
    __syncthreads();
    mu_out = smu; rs_out = srs;
}

// LN(images) -> g_x (fp32) + bf16 splits
__global__ void ln_img_k(const float* __restrict__ in) {
    size_t base = (size_t)blockIdx.x * SD_;
    const float* src = in + base;
    float mu, r;
    ln_stats(src, SD_, mu, r);
    for (int i = threadIdx.x; i < SD_; i += blockDim.x) {
        float v = (src[i] - mu) * r;
        g_x[base + i] = v;
        split_bf16(v, g_x_hi[base + i], g_x_lo[base + i]);
    }
}

// LN(skip) -> bf16 splits only
__global__ void ln_skip_k() {
    size_t base = (size_t)blockIdx.x * SD_;
    const float* src = g_skip + base;
    float mu, r;
    ln_stats(src, SD_, mu, r);
    for (int i = threadIdx.x; i < SD_; i += blockDim.x) {
        float v = (src[i] - mu) * r;
        split_bf16(v, g_y_hi[base + i], g_y_lo[base + i]);
    }
}

// per-head LN over (S, HD), in place on g_qkv
__global__ void ln_head_k() {
    float* p = g_qkv + (size_t)blockIdx.x * SHD_;
    float mu, r;
    ln_stats(p, SHD_, mu, r);
    for (int i = threadIdx.x; i < SHD_; i += blockDim.x)
        p[i] = (p[i] - mu) * r;
}

// ---------------- QKV projection (wmma bf16 x3-split) ----------------
// out[mat][b,h,s,e] = sum_d x[b,s,d] * w[mat][h][d,e]
// Block: 128m x 64n, K=384, BK=32, 256 threads (8 warps = 4mw x 2nw).
#define QKV_WLD 72
__global__ void __launch_bounds__(256) qkv_k(const float* __restrict__ w1,
                                             const float* __restrict__ w2,
                                             const float* __restrict__ w3) {
    __shared__ __align__(32) __nv_bfloat16 whi[32 * QKV_WLD];
    __shared__ __align__(32) __nv_bfloat16 wlo[32 * QKV_WLD];
    __shared__ __align__(32) float cbuf[128 * 68];
    const int m0  = blockIdx.x * 128;
    const int h   = blockIdx.y;
    const int mat = blockIdx.z;
    const float* w = (mat == 0 ? w1 : (mat == 1 ? w2 : w3)) + (size_t)h * (D_ * HD_);
    const int tid = threadIdx.x;
    const int wid = tid >> 5;
    const int mw = wid >> 1, nw = wid & 1;

    wmma::fragment<wmma::accumulator, 16, 16, 16, float> acc[2][2];
#pragma unroll
    for (int i = 0; i < 2; i++)
#pragma unroll
        for (int j = 0; j < 2; j++) wmma::fill_fragment(acc[i][j], 0.f);

    for (int k0 = 0; k0 < D_; k0 += 32) {
        __syncthreads();
        for (int i = tid; i < 32 * 64; i += 256) {
            int kk = i >> 6, e = i & 63;
            float v = w[(size_t)(k0 + kk) * HD_ + e];
            split_bf16(v, whi[kk * QKV_WLD + e], wlo[kk * QKV_WLD + e]);
        }
        __syncthreads();
#pragma unroll
        for (int kf = 0; kf < 2; kf++) {
            int kg = k0 + kf * 16;
            wmma::fragment<wmma::matrix_a, 16, 16, 16, __nv_bfloat16, wmma::row_major> ah[2], al[2];
            wmma::fragment<wmma::matrix_b, 16, 16, 16, __nv_bfloat16, wmma::row_major> bh[2], bl[2];
#pragma unroll
            for (int i = 0; i < 2; i++) {
                int mrow = m0 + mw * 32 + i * 16;
                wmma::load_matrix_sync(ah[i], g_x_hi + (size_t)mrow * D_ + kg, D_);
                wmma::load_matrix_sync(al[i], g_x_lo + (size_t)mrow * D_ + kg, D_);
            }
#pragma unroll
            for (int j = 0; j < 2; j++) {
                int nc = nw * 32 + j * 16;
                wmma::load_matrix_sync(bh[j], whi + (kf * 16) * QKV_WLD + nc, QKV_WLD);
                wmma::load_matrix_sync(bl[j], wlo + (kf * 16) * QKV_WLD + nc, QKV_WLD);
            }
#pragma unroll
            for (int i = 0; i < 2; i++)
#pragma unroll
                for (int j = 0; j < 2; j++) {
                    wmma::mma_sync(acc[i][j], ah[i], bh[j], acc[i][j]);
                    wmma::mma_sync(acc[i][j], ah[i], bl[j], acc[i][j]);
                    wmma::mma_sync(acc[i][j], al[i], bh[j], acc[i][j]);
                }
        }
    }
    __syncthreads();
#pragma unroll
    for (int i = 0; i < 2; i++)
#pragma unroll
        for (int j = 0; j < 2; j++)
            wmma::store_matrix_sync(cbuf + (mw * 32 + i * 16) * 68 + nw * 32 + j * 16,
                                    acc[i][j], 68, wmma::mem_row_major);
    __syncthreads();
    float* outbase = g_qkv + (size_t)(mat * BH_) * SHD_;
    for (int idx = tid; idx < 128 * 16; idx += 256) {
        int mm = idx >> 4, e4 = idx & 15;
        int m = m0 + mm;
        if (m < BS_) {
            int bb = m / S_, s = m % S_;
            float4 v = *(float4*)(cbuf + mm * 68 + e4 * 4);
            *(float4*)(outbase + (size_t)(bb * H_ + h) * SHD_ + s * HD_ + e4 * 4) = v;
        }
    }
}

// ---------------- Fused attention per (b,h) (round-14 version, 234us) ----------------
#define KP_ 68
#define AT_THREADS 512
#define ATTN_SMEM_FLOATS (2 * S_ * KP_ + 512 + 1600 + 64 + 64 + 8 + 8 + 4096)
#define ATTN_SMEM_BYTES  (ATTN_SMEM_FLOATS * 4)

__global__ void __launch_bounds__(AT_THREADS, 1) attn_k() {
    extern __shared__ float sm[];
    float* Ks     = sm;                       // S*KP
    float* Vs     = Ks + S_ * KP_;            // S*KP
    float* qs     = Vs + S_ * KP_;            // 512 : [r][e]  (8 rows x 64)
    float* ps     = qs + 512;                 // 1600: [t][r]  (t*8 + r), t < 197
    float* rmax   = ps + 1600;                // 64  : [r][wid<7]
    float* rsum   = rmax + 64;                // 64
    float* rowmax = rsum + 64;                // 8
    float* rowsum = rowmax + 8;               // 8
    float* obuf   = rowsum + 8;               // 4096: [part][r][e]

    const int bh   = blockIdx.x;
    const int tid  = threadIdx.x;
    const int lane = tid & 31, wid = tid >> 5;
    const float* qg = g_qkv + (size_t)bh * SHD_;
    const float* kg = g_qkv + (size_t)(BH_ + bh) * SHD_;
    const float* vg = g_qkv + (size_t)(2 * BH_ + bh) * SHD_;

    for (int idx = tid; idx < SHD_; idx += AT_THREADS) {
        int t = idx >> 6, e = idx & 63;
        Ks[t * KP_ + e] = kg[idx];
        Vs[t * KP_ + e] = vg[idx];
    }
    const int bb = bh / H_, hh = bh % H_;
    const float scale = rsqrtf((float)S_);
    const float* xres = g_x + (size_t)bb * SD_;
    float* outp = g_skip + (size_t)bb * SD_;

    const int t = tid;

    for (int r0 = 0; r0 < S_; r0 += 8) {
        {
            int r = tid >> 6, e = tid & 63;
            int row = r0 + r;
            qs[tid] = (row < S_) ? qg[row * HD_ + e] : 0.f;
        }
        __syncthreads();

        float sc[8];
        {
            u64 acc[8];
#pragma unroll
            for (int r = 0; r < 8; r++) acc[r] = 0ull;
            if (t < S_) {
                const ulonglong2* kr = (const ulonglong2*)(Ks + t * KP_);
                const ulonglong2* q2 = (const ulonglong2*)qs;
#pragma unroll
                for (int ee = 0; ee < 16; ee++) {
                    ulonglong2 kv = kr[ee];
#pragma unroll
                    for (int r = 0; r < 8; r++) {
                        ulonglong2 qv = q2[r * 16 + ee];
                        FMA2(acc[r], kv.x, qv.x);
                        FMA2(acc[r], kv.y, qv.y);
                    }
                }
            }
#pragma unroll
            for (int r = 0; r < 8; r++) {
                float2 v = unpack2(acc[r]);
                sc[r] = (t < S_) ? (v.x + v.y) * scale : -1e30f;
            }
        }
        if (wid < 7) {
#pragma unroll
            for (int r = 0; r < 8; r++) {
                float m = sc[r];
#pragma unroll
                for (int o = 16; o; o >>= 1)
                    m = fmaxf(m, __shfl_xor_sync(0xffffffffu, m, o));
                if (lane == 0) rmax[r * 8 + wid] = m;
            }
        }
        __syncthreads();
        if (tid < 8) {
            float mm = -1e30f;
#pragma unroll
            for (int wq = 0; wq < 7; wq++) mm = fmaxf(mm, rmax[tid * 8 + wq]);
            rowmax[tid] = mm;
        }
        __syncthreads();
        float ex[8];
#pragma unroll
        for (int r = 0; r < 8; r++)
            ex[r] = (t < S_) ? __expf(sc[r] - rowmax[r]) : 0.f;
        if (t < S_) {
            *(float4*)(ps + t * 8)     = make_float4(ex[0], ex[1], ex[2], ex[3]);
            *(float4*)(ps + t * 8 + 4) = make_float4(ex[4], ex[5], ex[6], ex[7]);
        }
        if (wid < 7) {
#pragma unroll
            for (int r = 0; r < 8; r++) {
                float s = ex[r];
#pragma unroll
                for (int o = 16; o; o >>= 1)
                    s += __shfl_xor_sync(0xffffffffu, s, o);
                if (lane == 0) rsum[r * 8 + wid] = s;
            }
        }
        __syncthreads();
        if (tid < 8) {
            float ss = 0.f;
#pragma unroll
            for (int wq = 0; wq < 7; wq++) ss += rsum[tid * 8 + wq];
            rowsum[tid] = ss;
        }
        {
            int e = tid & 63, part = tid >> 6;
            float a[8];
#pragma unroll
            for (int r = 0; r < 8; r++) a[r] = 0.f;
            for (int tt = part; tt < S_; tt += 8) {
                float vv = Vs[tt * KP_ + e];
                float4 p0 = *(const float4*)(ps + tt * 8);
                float4 p1 = *(const float4*)(ps + tt * 8 + 4);
                a[0] += p0.x * vv; a[1] += p0.y * vv;
                a[2] += p0.z * vv; a[3] += p0.w * vv;
                a[4] += p1.x * vv; a[5] += p1.y * vv;
                a[6] += p1.z * vv; a[7] += p1.w * vv;
            }
#pragma unroll
            for (int r = 0; r < 8; r++) obuf[part * 512 + r * 64 + e] = a[r];
        }
        __syncthreads();
        {
            int r = tid >> 6, e = tid & 63;
            int row = r0 + r;
            if (row < S_) {
                float o = 0.f;
#pragma unroll
                for (int part = 0; part < 8; part++)
                    o += obuf[part * 512 + r * 64 + e];
                o /= rowsum[r];
                int off = row * D_ + hh * HD_ + e;
                outp[off] = o + xres[off];
            }
        }
    }
}

// ---------------- MLP GEMM 1 (wmma, split-K partials) ----------------
// g_part[chunk][32][1024] = y[32, chunk] @ W1[chunk, 1024]
// Block: 32m x 128n, K-chunk 384, BK=32, 256 threads (warp nw=wid owns 16 cols).
#define MLP_WLD 136
__global__ void __launch_bounds__(256) mlp1_k(const float* __restrict__ w1) {
    __shared__ __align__(32) __nv_bfloat16 whi[32 * MLP_WLD];
    __shared__ __align__(32) __nv_bfloat16 wlo[32 * MLP_WLD];
    const int n0 = blockIdx.x * 128;
    const int kbase = blockIdx.y * KCH_;
    const int tid = threadIdx.x, wid = tid >> 5;

    wmma::fragment<wmma::accumulator, 16, 16, 16, float> acc[2];
    wmma::fill_fragment(acc[0], 0.f);
    wmma::fill_fragment(acc[1], 0.f);

    for (int k0 = 0; k0 < KCH_; k0 += 32) {
        __syncthreads();
        for (int i = tid; i < 32 * 128; i += 256) {
            int kk = i >> 7, e = i & 127;
            float v = w1[(size_t)(kbase + k0 + kk) * HID_ + n0 + e];
            split_bf16(v, whi[kk * MLP_WLD + e], wlo[kk * MLP_WLD + e]);
        }
        __syncthreads();
#pragma unroll
        for (int kf = 0; kf < 2; kf++) {
            int kg = kbase + k0 + kf * 16;
            wmma::fragment<wmma::matrix_a, 16, 16, 16, __nv_bfloat16, wmma::row_major> ah[2], al[2];
            wmma::fragment<wmma::matrix_b, 16, 16, 16, __nv_bfloat16, wmma::row_major> bh, bl;
#pragma unroll
            for (int i = 0; i < 2; i++) {
                wmma::load_matrix_sync(ah[i], g_y_hi + (size_t)(i * 16) * SD_ + kg, SD_);
                wmma::load_matrix_sync(al[i], g_y_lo + (size_t)(i * 16) * SD_ + kg, SD_);
            }
            wmma::load_matrix_sync(bh, whi + (kf * 16) * MLP_WLD + wid * 16, MLP_WLD);
            wmma::load_matrix_sync(bl, wlo + (kf * 16) * MLP_WLD + wid * 16, MLP_WLD);
#pragma unroll
            for (int i = 0; i < 2; i++) {
                wmma::mma_sync(acc[i], ah[i], bh, acc[i]);
                wmma::mma_sync(acc[i], ah[i], bl, acc[i]);
                wmma::mma_sync(acc[i], al[i], bh, acc[i]);
            }
        }
    }
    float* pp = g_part + (size_t)blockIdx.y * (B_ * HID_) + n0 + wid * 16;
    wmma::store_matrix_sync(pp, acc[0], HID_, wmma::mem_row_major);
    wmma::store_matrix_sync(pp + (size_t)16 * HID_, acc[1], HID_, wmma::mem_row_major);
}

// ---------------- reduce split-K + bias + GELU -> g_h (bf16 splits) ----------------
__global__ void reduce1_k(const float* __restrict__ b1) {
    int idx = blockIdx.x * 256 + threadIdx.x;   // 0..32767, = m*1024 + j
    float s = 0.f;
#pragma unroll 4
    for (int c = 0; c < SPLITK_; c++) s += g_part[(size_t)c * (B_ * HID_) + idx];
    int j = idx & 1023;
    s += b1[j];
    float g = s * normcdff(s);
    split_bf16(g, g_h_hi[idx], g_h_lo[idx]);
}

// ---------------- MLP GEMM 2 (wmma) + bias + GELU + skip ----------------
// out[32, SD] = skip + gelu(h[32,1024] @ W2[1024, SD] + b2)
// Block: 32m x 128n, K=1024, BK=32, 256 threads.
__global__ void __launch_bounds__(256) mlp2_k(const float* __restrict__ w2,
                                              const float* __restrict__ b2,
                                              float* __restrict__ out) {
    __shared__ __align__(32) __nv_bfloat16 wsm[2 * 32 * MLP_WLD];  // whi | wlo
    __nv_bfloat16* whi = wsm;
    __nv_bfloat16* wlo = wsm + 32 * MLP_WLD;
    const int n0 = blockIdx.x * 128;
    const int tid = threadIdx.x, wid = tid >> 5;

    wmma::fragment<wmma::accumulator, 16, 16, 16, float> acc[2];
    wmma::fill_fragment(acc[0], 0.f);
    wmma::fill_fragment(acc[1], 0.f);

    for (int k0 = 0; k0 < HID_; k0 += 32) {
        __syncthreads();
        for (int i = tid; i < 32 * 128; i += 256) {
            int kk = i >> 7, e = i & 127;
            float v = w2[(size_t)(k0 + kk) * SD_ + n0 + e];
            split_bf16(v, whi[kk * MLP_WLD + e], wlo[kk * MLP_WLD + e]);
        }
        __syncthreads();
#pragma unroll
        for (int kf = 0; kf < 2; kf++) {
            int kg = k0 + kf * 16;
            wmma::fragment<wmma::matrix_a, 16, 16, 16, __nv_bfloat16, wmma::row_major> ah[2], al[2];
            wmma::fragment<wmma::matrix_b, 16, 16, 16, __nv_bfloat16, wmma::row_major> bh, bl;
#pragma unroll
            for (int i = 0; i < 2; i++) {
                wmma::load_matrix_sync(ah[i], g_h_hi + (size_t)(i * 16) * HID_ + kg, HID_);
                wmma::load_matrix_sync(al[i], g_h_lo + (size_t)(i * 16) * HID_ + kg, HID_);
            }
            wmma::load_matrix_sync(bh, whi + (kf * 16) * MLP_WLD + wid * 16, MLP_WLD);
            wmma::load_matrix_sync(bl, wlo + (kf * 16) * MLP_WLD + wid * 16, MLP_WLD);
#pragma unroll
            for (int i = 0; i < 2; i++) {
                wmma::mma_sync(acc[i], ah[i], bh, acc[i]);
                wmma::mma_sync(acc[i], ah[i], bl, acc[i]);
                wmma::mma_sync(acc[i], al[i], bh, acc[i]);
            }
        }
    }
    // epilogue: stash C in smem (aliasing the weight buffers), then fused writeback
    __syncthreads();
    float* cbuf = (float*)wsm;   // 32 x MLP_WLD floats = 17408 B, fits exactly
    wmma::store_matrix_sync(cbuf + wid * 16, acc[0], MLP_WLD, wmma::mem_row_major);
    wmma::store_matrix_sync(cbuf + 16 * MLP_WLD + wid * 16, acc[1], MLP_WLD, wmma::mem_row_major);
    __syncthreads();
    for (int idx = tid; idx < 32 * 32; idx += 256) {
        int mm = idx >> 5, q = idx & 31;   // row, col-quad
        int n = n0 + q * 4;
        float4 c = *(float4*)(cbuf + mm * MLP_WLD + q * 4);
        float4 bias = *(const float4*)(b2 + n);
        float4 sk = *(const float4*)(g_skip + (size_t)mm * SD_ + n);
        float s0 = c.x + bias.x, s1 = c.y + bias.y, s2 = c.z + bias.z, s3 = c.w + bias.w;
        float4 r;
        r.x = sk.x + s0 * normcdff(s0);
        r.y = sk.y + s1 * normcdff(s1);
        r.z = sk.z + s2 * normcdff(s2);
        r.w = sk.w + s3 * normcdff(s3);
        *(float4*)(out + (size_t)mm * SD_ + n) = r;
    }
}

// ---------------- launch ----------------
extern "C" void kernel_launch(void* const* d_in, const int* in_sizes, int n_in,
                              void* d_out, int out_size) {
    const float* images = (const float*)d_in[0];
    const float* w1     = (const float*)d_in[1];
    const float* w2     = (const float*)d_in[2];
    const float* w3     = (const float*)d_in[3];
    const float* mlp_w1 = (const float*)d_in[4];
    const float* mlp_b1 = (const float*)d_in[5];
    const float* mlp_w2 = (const float*)d_in[6];
    const float* mlp_b2 = (const float*)d_in[7];
    float* out = (float*)d_out;

    cudaFuncSetAttribute(attn_k, cudaFuncAttributeMaxDynamicSharedMemorySize,
                         ATTN_SMEM_BYTES);

    ln_img_k<<<B_, 1024>>>(images);
    qkv_k<<<dim3(50, H_, 3), 256>>>(w1, w2, w3);
    ln_head_k<<<3 * BH_, 512>>>();
    attn_k<<<BH_, AT_THREADS, ATTN_SMEM_BYTES>>>();
    ln_skip_k<<<B_, 1024>>>();
    mlp1_k<<<dim3(HID_ / 128, SPLITK_), 256>>>(mlp_w1);
    reduce1_k<<<(B_ * HID_) / 256, 256>>>(mlp_b1);
    mlp2_k<<<SD_ / 128, 256>>>(mlp_w2, mlp_b2, out);
}